// round 1
// baseline (speedup 1.0000x reference)
#include <cuda_runtime.h>
#include <math.h>

#define BB 4
#define CC 64
#define NN 4096

// Scratch for Q, K, V  ([B][C][N] each, 4 MB apiece)
__device__ float g_Q[BB*CC*NN];
__device__ float g_K[BB*CC*NN];
__device__ float g_V[BB*CC*NN];

// ---------------------------------------------------------------------------
// Kernel 1: QKV projection.  q[b,o,n] = sum_c W[o,c] * x[b,c,n] + b[o]
// grid (32, 4), 256 threads.  Tile: 64 out-channels x 128 n per block.
// ---------------------------------------------------------------------------
__global__ void __launch_bounds__(256) qkv_kernel(
    const float* __restrict__ x,
    const float* __restrict__ Wq, const float* __restrict__ bq,
    const float* __restrict__ Wk, const float* __restrict__ bk,
    const float* __restrict__ Wv, const float* __restrict__ bv)
{
    extern __shared__ float sm[];
    float* xs  = sm;               // [64][128]
    float* wtq = sm + 64*128;      // [64][68]  W^T, padded pitch
    float* wtk = wtq + 64*68;
    float* wtv = wtk + 64*68;

    const int t = threadIdx.x;
    const int b = blockIdx.y;
    const int nbase = blockIdx.x * 128;

    // Load W transposed (coalesced global read; one-time smem write conflicts OK)
    for (int idx = t; idx < 64*64; idx += 256) {
        int o = idx >> 6, c = idx & 63;
        wtq[c*68 + o] = Wq[idx];
        wtk[c*68 + o] = Wk[idx];
        wtv[c*68 + o] = Wv[idx];
    }
    // Load x tile [c][n] (n contiguous)
    const float* xb = x + (size_t)b*CC*NN + nbase;
    for (int idx4 = t; idx4 < (64*128)/4; idx4 += 256) {
        int c = idx4 >> 5, n4 = (idx4 & 31) << 2;
        *(float4*)&xs[c*128 + n4] = *(const float4*)&xb[(size_t)c*NN + n4];
    }
    __syncthreads();

    const int ty = t >> 4, tx = t & 15;
    const int o0 = ty * 4, n0 = tx * 8;

    float aq[4][8], ak[4][8], av[4][8];
    #pragma unroll
    for (int r = 0; r < 4; r++) {
        float vq = bq[o0+r], vk = bk[o0+r], vv = bv[o0+r];
        #pragma unroll
        for (int s = 0; s < 8; s++) { aq[r][s]=vq; ak[r][s]=vk; av[r][s]=vv; }
    }

    #pragma unroll 4
    for (int c = 0; c < 64; c++) {
        float wqa[4], wka[4], wva[4], xr[8];
        *(float4*)&wqa[0] = *(float4*)&wtq[c*68 + o0];
        *(float4*)&wka[0] = *(float4*)&wtk[c*68 + o0];
        *(float4*)&wva[0] = *(float4*)&wtv[c*68 + o0];
        *(float4*)&xr[0]  = *(float4*)&xs[c*128 + n0];
        *(float4*)&xr[4]  = *(float4*)&xs[c*128 + n0 + 4];
        #pragma unroll
        for (int r = 0; r < 4; r++)
            #pragma unroll
            for (int s = 0; s < 8; s++) {
                aq[r][s] += wqa[r]*xr[s];
                ak[r][s] += wka[r]*xr[s];
                av[r][s] += wva[r]*xr[s];
            }
    }

    const size_t base = (size_t)b*CC*NN + nbase + n0;
    #pragma unroll
    for (int r = 0; r < 4; r++) {
        size_t off = base + (size_t)(o0+r)*NN;
        *(float4*)&g_Q[off]   = *(float4*)&aq[r][0];
        *(float4*)&g_Q[off+4] = *(float4*)&aq[r][4];
        *(float4*)&g_K[off]   = *(float4*)&ak[r][0];
        *(float4*)&g_K[off+4] = *(float4*)&ak[r][4];
        *(float4*)&g_V[off]   = *(float4*)&av[r][0];
        *(float4*)&g_V[off+4] = *(float4*)&av[r][4];
    }
}

// ---------------------------------------------------------------------------
// Kernel 2: fused flash attention + epilogue (gamma*out + x).
// grid (32, 4), 256 threads; 128 queries/CTA, 128-key tiles.
// S[i,j] = sum_c Q[c,i]K[c,j]; online softmax; O[i,c] += P[i,j] V[c,j].
// Thread (ty,tx): S rows i0=8ty, S cols j0=8tx; O rows i0=8ty, O cols c0=4tx.
// ---------------------------------------------------------------------------
__global__ void __launch_bounds__(256) attn_kernel(
    const float* __restrict__ x, const float* __restrict__ gamma,
    float* __restrict__ out)
{
    extern __shared__ float sm[];
    float* Qs = sm;            // [64][128]
    float* Ks = sm + 8192;     // [64][128]
    float* Vt = sm + 16384;    // [128][65]  V transposed, padded pitch
    float* Pt = sm + 24704;    // [128][128] P transposed, XOR-swizzled rows

    const int t = threadIdx.x;
    const int b = blockIdx.y;
    const int ibase = blockIdx.x * 128;
    const int ty = t >> 4, tx = t & 15;
    const int i0 = ty*8, j0 = tx*8, c0 = tx*4;

    const float* Qg = g_Q + (size_t)b*CC*NN;
    const float* Kg = g_K + (size_t)b*CC*NN;
    const float* Vg = g_V + (size_t)b*CC*NN;

    // Load Q tile [c][i]
    for (int idx4 = t; idx4 < 2048; idx4 += 256) {
        int c = idx4 >> 5, i4 = (idx4 & 31) << 2;
        *(float4*)&Qs[c*128 + i4] = *(const float4*)&Qg[(size_t)c*NN + ibase + i4];
    }

    float O[8][4];
    float m[8], l[8];
    #pragma unroll
    for (int r = 0; r < 8; r++) {
        m[r] = -INFINITY; l[r] = 0.f;
        #pragma unroll
        for (int cc = 0; cc < 4; cc++) O[r][cc] = 0.f;
    }

    const int fsw = tx & 7;  // swizzle key for this thread's P columns (j0>>3 & 7)

    for (int jt = 0; jt < NN; jt += 128) {
        __syncthreads();   // Ks/Vt consumers from previous iter done (also covers Qs 1st iter)
        // Load K tile [c][j]
        for (int idx4 = t; idx4 < 2048; idx4 += 256) {
            int c = idx4 >> 5, j4 = (idx4 & 31) << 2;
            *(float4*)&Ks[c*128 + j4] = *(const float4*)&Kg[(size_t)c*NN + jt + j4];
        }
        // Load V transposed: Vt[j][c], pitch 65 (conflict-free scalar pattern)
        for (int idx = t; idx < 8192; idx += 256) {
            int c = idx >> 7, j = idx & 127;
            Vt[j*65 + c] = Vg[(size_t)c*NN + jt + j];
        }
        __syncthreads();

        // ---- GEMM1: S = Q^T K ----
        float S[8][8];
        #pragma unroll
        for (int r = 0; r < 8; r++)
            #pragma unroll
            for (int s = 0; s < 8; s++) S[r][s] = 0.f;

        #pragma unroll 4
        for (int c = 0; c < 64; c++) {
            float q[8], k[8];
            *(float4*)&q[0] = *(float4*)&Qs[c*128 + i0];
            *(float4*)&q[4] = *(float4*)&Qs[c*128 + i0 + 4];
            *(float4*)&k[0] = *(float4*)&Ks[c*128 + j0];
            *(float4*)&k[4] = *(float4*)&Ks[c*128 + j0 + 4];
            #pragma unroll
            for (int r = 0; r < 8; r++)
                #pragma unroll
                for (int s = 0; s < 8; s++) S[r][s] += q[r]*k[s];
        }

        // ---- online softmax (row groups = 16-lane warp halves) ----
        #pragma unroll
        for (int r = 0; r < 8; r++) {
            float mx = S[r][0];
            #pragma unroll
            for (int s = 1; s < 8; s++) mx = fmaxf(mx, S[r][s]);
            #pragma unroll
            for (int d = 1; d < 16; d <<= 1)
                mx = fmaxf(mx, __shfl_xor_sync(0xffffffffu, mx, d));
            float mn = fmaxf(m[r], mx);
            float scale = __expf(m[r] - mn);
            float rs = 0.f;
            #pragma unroll
            for (int s = 0; s < 8; s++) { S[r][s] = __expf(S[r][s] - mn); rs += S[r][s]; }
            #pragma unroll
            for (int d = 1; d < 16; d <<= 1)
                rs += __shfl_xor_sync(0xffffffffu, rs, d);
            l[r] = l[r]*scale + rs;
            m[r] = mn;
            #pragma unroll
            for (int cc = 0; cc < 4; cc++) O[r][cc] *= scale;
        }

        // ---- store P transposed, swizzled: Pt[j][i], chunk (i>>2) ^= (j>>3)&7 ----
        #pragma unroll
        for (int jj = 0; jj < 8; jj++) {
            float* row = Pt + (j0 + jj)*128;
            int ca = (((2*ty)   ^ fsw) << 2);
            int cb = (((2*ty+1) ^ fsw) << 2);
            *(float4*)&row[ca] = make_float4(S[0][jj], S[1][jj], S[2][jj], S[3][jj]);
            *(float4*)&row[cb] = make_float4(S[4][jj], S[5][jj], S[6][jj], S[7][jj]);
        }
        __syncthreads();

        // ---- GEMM2: O[i,c] += sum_j P[i,j] * V[c,j] ----
        #pragma unroll 2
        for (int j = 0; j < 128; j++) {
            int fx = (j >> 3) & 7;
            const float* row = Pt + j*128;
            float pr[8];
            *(float4*)&pr[0] = *(const float4*)&row[(((2*ty)   ^ fx) << 2)];
            *(float4*)&pr[4] = *(const float4*)&row[(((2*ty+1) ^ fx) << 2)];
            float vv[4];
            #pragma unroll
            for (int cc = 0; cc < 4; cc++) vv[cc] = Vt[j*65 + c0 + cc];
            #pragma unroll
            for (int r = 0; r < 8; r++)
                #pragma unroll
                for (int cc = 0; cc < 4; cc++) O[r][cc] += pr[r]*vv[cc];
        }
    }

    // ---- epilogue: normalize, stage transposed, write gamma*out + x ----
    float rl[8];
    #pragma unroll
    for (int r = 0; r < 8; r++) rl[r] = 1.0f / l[r];

    __syncthreads();               // done reading Qs/Pt; reuse Qs as [c][i] staging
    #pragma unroll
    for (int r = 0; r < 8; r++)
        #pragma unroll
        for (int cc = 0; cc < 4; cc++)
            Qs[(c0+cc)*128 + i0 + r] = O[r][cc] * rl[r];
    __syncthreads();

    const float g = gamma[0];
    const float* xb = x   + (size_t)b*CC*NN + ibase;
    float*       ob = out + (size_t)b*CC*NN + ibase;
    for (int idx4 = t; idx4 < 2048; idx4 += 256) {
        int c = idx4 >> 5, i4 = (idx4 & 31) << 2;
        float4 o4 = *(float4*)&Qs[c*128 + i4];
        float4 x4 = *(const float4*)&xb[(size_t)c*NN + i4];
        o4.x = g*o4.x + x4.x;
        o4.y = g*o4.y + x4.y;
        o4.z = g*o4.z + x4.z;
        o4.w = g*o4.w + x4.w;
        *(float4*)&ob[(size_t)c*NN + i4] = o4;
    }
}

// ---------------------------------------------------------------------------
extern "C" void kernel_launch(void* const* d_in, const int* in_sizes, int n_in,
                              void* d_out, int out_size)
{
    const float* x     = (const float*)d_in[0];
    const float* Wq    = (const float*)d_in[1];
    const float* bq    = (const float*)d_in[2];
    const float* Wk    = (const float*)d_in[3];
    const float* bk    = (const float*)d_in[4];
    const float* Wv    = (const float*)d_in[5];
    const float* bv    = (const float*)d_in[6];
    const float* gamma = (const float*)d_in[7];
    float* out = (float*)d_out;

    const int smem1 = (64*128 + 3*64*68) * sizeof(float);           // 84,992 B
    const int smem2 = (64*128 + 64*128 + 128*65 + 128*128) * sizeof(float); // 164,352 B

    cudaFuncSetAttribute(qkv_kernel,  cudaFuncAttributeMaxDynamicSharedMemorySize, smem1);
    cudaFuncSetAttribute(attn_kernel, cudaFuncAttributeMaxDynamicSharedMemorySize, smem2);

    qkv_kernel<<<dim3(32, 4), 256, smem1>>>(x, Wq, bq, Wk, bk, Wv, bv);
    attn_kernel<<<dim3(32, 4), 256, smem2>>>(x, gamma, out);
}

// round 2
// speedup vs baseline: 1.1939x; 1.1939x over previous
#include <cuda_runtime.h>
#include <math.h>

#define BB 4
#define CC 64
#define NN 4096

typedef unsigned long long u64t;

__device__ float g_Q[BB*CC*NN];
__device__ float g_K[BB*CC*NN];
__device__ float g_V[BB*CC*NN];

// ---------------- f32x2 helpers (Blackwell packed fp32) ----------------
__device__ __forceinline__ u64t pk2(float a, float b) {
    u64t r; asm("mov.b64 %0,{%1,%2};" : "=l"(r) : "f"(a), "f"(b)); return r;
}
__device__ __forceinline__ void up2(u64t p, float& a, float& b) {
    asm("mov.b64 {%0,%1},%2;" : "=f"(a), "=f"(b) : "l"(p));
}
__device__ __forceinline__ void ffma2(u64t& d, u64t a, u64t b) {
    asm("fma.rn.f32x2 %0,%1,%2,%0;" : "+l"(d) : "l"(a), "l"(b));
}
__device__ __forceinline__ void fmul2(u64t& d, u64t s) {
    asm("mul.rn.f32x2 %0,%0,%1;" : "+l"(d) : "l"(s));
}
__device__ __forceinline__ void lds_v2u64(u64t& a, u64t& b, unsigned addr) {
    asm volatile("ld.shared.v2.u64 {%0,%1},[%2];" : "=l"(a), "=l"(b) : "r"(addr));
}

// ---------------------------------------------------------------------------
// Kernel 1: QKV projection (unchanged from R1 — small fraction of runtime)
// ---------------------------------------------------------------------------
__global__ void __launch_bounds__(256) qkv_kernel(
    const float* __restrict__ x,
    const float* __restrict__ Wq, const float* __restrict__ bq,
    const float* __restrict__ Wk, const float* __restrict__ bk,
    const float* __restrict__ Wv, const float* __restrict__ bv)
{
    extern __shared__ float sm[];
    float* xs  = sm;               // [64][128]
    float* wtq = sm + 64*128;      // [64][68]
    float* wtk = wtq + 64*68;
    float* wtv = wtk + 64*68;

    const int t = threadIdx.x;
    const int b = blockIdx.y;
    const int nbase = blockIdx.x * 128;

    for (int idx = t; idx < 64*64; idx += 256) {
        int o = idx >> 6, c = idx & 63;
        wtq[c*68 + o] = Wq[idx];
        wtk[c*68 + o] = Wk[idx];
        wtv[c*68 + o] = Wv[idx];
    }
    const float* xb = x + (size_t)b*CC*NN + nbase;
    for (int idx4 = t; idx4 < (64*128)/4; idx4 += 256) {
        int c = idx4 >> 5, n4 = (idx4 & 31) << 2;
        *(float4*)&xs[c*128 + n4] = *(const float4*)&xb[(size_t)c*NN + n4];
    }
    __syncthreads();

    const int ty = t >> 4, tx = t & 15;
    const int o0 = ty * 4, n0 = tx * 8;

    float aq[4][8], ak[4][8], av[4][8];
    #pragma unroll
    for (int r = 0; r < 4; r++) {
        float vq = bq[o0+r], vk = bk[o0+r], vv = bv[o0+r];
        #pragma unroll
        for (int s = 0; s < 8; s++) { aq[r][s]=vq; ak[r][s]=vk; av[r][s]=vv; }
    }

    #pragma unroll 4
    for (int c = 0; c < 64; c++) {
        float wqa[4], wka[4], wva[4], xr[8];
        *(float4*)&wqa[0] = *(float4*)&wtq[c*68 + o0];
        *(float4*)&wka[0] = *(float4*)&wtk[c*68 + o0];
        *(float4*)&wva[0] = *(float4*)&wtv[c*68 + o0];
        *(float4*)&xr[0]  = *(float4*)&xs[c*128 + n0];
        *(float4*)&xr[4]  = *(float4*)&xs[c*128 + n0 + 4];
        #pragma unroll
        for (int r = 0; r < 4; r++)
            #pragma unroll
            for (int s = 0; s < 8; s++) {
                aq[r][s] += wqa[r]*xr[s];
                ak[r][s] += wka[r]*xr[s];
                av[r][s] += wva[r]*xr[s];
            }
    }

    const size_t base = (size_t)b*CC*NN + nbase + n0;
    #pragma unroll
    for (int r = 0; r < 4; r++) {
        size_t off = base + (size_t)(o0+r)*NN;
        *(float4*)&g_Q[off]   = *(float4*)&aq[r][0];
        *(float4*)&g_Q[off+4] = *(float4*)&aq[r][4];
        *(float4*)&g_K[off]   = *(float4*)&ak[r][0];
        *(float4*)&g_K[off+4] = *(float4*)&ak[r][4];
        *(float4*)&g_V[off]   = *(float4*)&av[r][0];
        *(float4*)&g_V[off+4] = *(float4*)&av[r][4];
    }
}

// ---------------------------------------------------------------------------
// Kernel 2: flash attention, warp-row layout + f32x2 packed FMA.
// 8 warps, warp w owns query rows [16w, 16w+16). 128-query x 128-key tiles.
// GEMM1: lane owns 4 consecutive key cols; S packed in f32x2 along row pairs.
// GEMM2: lane owns out-channels {lane, lane+32}; O packed in f32x2 along
//        j-parity (even/odd partial sums), one horizontal add at the end.
// smem floats: Qs[64][128] | Ks[64][128] | Vs[64][128] (chunk-XOR-swizzled)
//              | Ps[128][128]   -> 40960 floats = 163,840 B
// ---------------------------------------------------------------------------
__global__ void __launch_bounds__(256) attn_kernel(
    const float* __restrict__ x, const float* __restrict__ gamma,
    float* __restrict__ out)
{
    extern __shared__ float sm[];
    float* Qs = sm;                 // [64][128]
    float* Ks = sm + 8192;          // [64][128]
    float* Vs = sm + 16384;         // [64][128], 16B-chunk swizzle: chunk j>>2 ^ (c&31)
    float* Ps = sm + 24576;         // [128][128]

    const unsigned sbase = (unsigned)__cvta_generic_to_shared(sm);
    const unsigned sQ = sbase;
    const unsigned sV = sbase + 16384u*4u;
    const unsigned sP = sbase + 24576u*4u;

    const int t = threadIdx.x;
    const int b = blockIdx.y;
    const int ibase = blockIdx.x * 128;
    const int wid = t >> 5, lane = t & 31;
    const int i0 = wid * 16;        // this warp's query rows
    const int j0 = lane * 4;        // this lane's key cols in GEMM1

    const float* Qg = g_Q + (size_t)b*CC*NN;
    const float* Kg = g_K + (size_t)b*CC*NN;
    const float* Vg = g_V + (size_t)b*CC*NN;

    // Load Q tile [c][i]
    for (int idx4 = t; idx4 < 2048; idx4 += 256) {
        int c = idx4 >> 5, i4 = (idx4 & 31) << 2;
        *(float4*)&Qs[c*128 + i4] = *(const float4*)&Qg[(size_t)c*NN + ibase + i4];
    }

    // O accumulators: O2[r][cc] = f32x2 partial sums (even-j, odd-j) for
    // row i0+r, out-channel cc==0 ? lane : lane+32
    u64t O2[16][2];
    float m[16], l[16];
    #pragma unroll
    for (int r = 0; r < 16; r++) {
        m[r] = -INFINITY; l[r] = 0.f;
        O2[r][0] = 0ull; O2[r][1] = 0ull;
    }

    for (int jt = 0; jt < NN; jt += 128) {
        __syncthreads();   // prev GEMM2 done with Ks/Vs/Ps (and Q load on iter 0... Q guarded by next sync)
        // Load K tile [c][j]
        for (int idx4 = t; idx4 < 2048; idx4 += 256) {
            int c = idx4 >> 5, j4 = (idx4 & 31) << 2;
            *(float4*)&Ks[c*128 + j4] = *(const float4*)&Kg[(size_t)c*NN + jt + j4];
        }
        // Load V tile [c][j], 16B-chunk XOR swizzle for conflict-free row reads
        for (int idx4 = t; idx4 < 2048; idx4 += 256) {
            int c = idx4 >> 5, jc = idx4 & 31;
            *(float4*)&Vs[c*128 + 4*(jc ^ (c & 31))] =
                *(const float4*)&Vg[(size_t)c*NN + jt + 4*jc];
        }
        __syncthreads();

        // ---- GEMM1: S[i,j] = sum_c Q[c,i] K[c,j], f32x2 pairs along i ----
        u64t S2[8][4];
        #pragma unroll
        for (int r2 = 0; r2 < 8; r2++)
            #pragma unroll
            for (int s = 0; s < 4; s++) S2[r2][s] = 0ull;

        #pragma unroll 4
        for (int c = 0; c < 64; c++) {
            u64t q2[8];
            unsigned qa = sQ + (unsigned)((c*128 + i0) * 4);
            lds_v2u64(q2[0], q2[1], qa);
            lds_v2u64(q2[2], q2[3], qa + 16);
            lds_v2u64(q2[4], q2[5], qa + 32);
            lds_v2u64(q2[6], q2[7], qa + 48);
            float4 kf = *(const float4*)&Ks[c*128 + j0];
            u64t kd0 = pk2(kf.x, kf.x), kd1 = pk2(kf.y, kf.y);
            u64t kd2 = pk2(kf.z, kf.z), kd3 = pk2(kf.w, kf.w);
            #pragma unroll
            for (int r2 = 0; r2 < 8; r2++) {
                ffma2(S2[r2][0], q2[r2], kd0);
                ffma2(S2[r2][1], q2[r2], kd1);
                ffma2(S2[r2][2], q2[r2], kd2);
                ffma2(S2[r2][3], q2[r2], kd3);
            }
        }

        // ---- online softmax: full-warp row reductions (rows span 32 lanes) ----
        #pragma unroll
        for (int r2 = 0; r2 < 8; r2++) {
            const int ra = 2*r2, rb = 2*r2 + 1;
            float A[4], Bv[4];
            up2(S2[r2][0], A[0], Bv[0]);
            up2(S2[r2][1], A[1], Bv[1]);
            up2(S2[r2][2], A[2], Bv[2]);
            up2(S2[r2][3], A[3], Bv[3]);

            float mxa = fmaxf(fmaxf(A[0], A[1]), fmaxf(A[2], A[3]));
            float mxb = fmaxf(fmaxf(Bv[0], Bv[1]), fmaxf(Bv[2], Bv[3]));
            #pragma unroll
            for (int d = 16; d >= 1; d >>= 1) {
                mxa = fmaxf(mxa, __shfl_xor_sync(0xffffffffu, mxa, d));
                mxb = fmaxf(mxb, __shfl_xor_sync(0xffffffffu, mxb, d));
            }
            float mna = fmaxf(m[ra], mxa), mnb = fmaxf(m[rb], mxb);
            float sca = __expf(m[ra] - mna), scb = __expf(m[rb] - mnb);
            float rsa = 0.f, rsb = 0.f;
            #pragma unroll
            for (int s = 0; s < 4; s++) {
                A[s]  = __expf(A[s]  - mna); rsa += A[s];
                Bv[s] = __expf(Bv[s] - mnb); rsb += Bv[s];
            }
            #pragma unroll
            for (int d = 16; d >= 1; d >>= 1) {
                rsa += __shfl_xor_sync(0xffffffffu, rsa, d);
                rsb += __shfl_xor_sync(0xffffffffu, rsb, d);
            }
            l[ra] = l[ra]*sca + rsa;  m[ra] = mna;
            l[rb] = l[rb]*scb + rsb;  m[rb] = mnb;

            u64t s2a = pk2(sca, sca), s2b = pk2(scb, scb);
            fmul2(O2[ra][0], s2a); fmul2(O2[ra][1], s2a);
            fmul2(O2[rb][0], s2b); fmul2(O2[rb][1], s2b);

            *(float4*)&Ps[(i0+ra)*128 + j0] = make_float4(A[0], A[1], A[2], A[3]);
            *(float4*)&Ps[(i0+rb)*128 + j0] = make_float4(Bv[0], Bv[1], Bv[2], Bv[3]);
        }
        __syncthreads();

        // ---- GEMM2: O[i,c] += sum_j P[i,j] V[c,j], f32x2 pairs along j ----
        #pragma unroll 2
        for (int j = 0; j < 128; j += 4) {
            u64t pA[16], pB[16];
            #pragma unroll
            for (int r = 0; r < 16; r++)
                lds_v2u64(pA[r], pB[r], sP + (unsigned)(((i0 + r)*128 + j) * 4));
            u64t vA, vB, vC, vD;
            // swizzled V: row c, cols j..j+3 live at chunk (j>>2)^(c&31)
            lds_v2u64(vA, vB, sV + (unsigned)((lane*128 + 4*((j >> 2) ^ lane)) * 4));
            lds_v2u64(vC, vD, sV + (unsigned)(((lane+32)*128 + 4*((j >> 2) ^ lane)) * 4));
            #pragma unroll
            for (int r = 0; r < 16; r++) {
                ffma2(O2[r][0], pA[r], vA);
                ffma2(O2[r][0], pB[r], vB);
                ffma2(O2[r][1], pA[r], vC);
                ffma2(O2[r][1], pB[r], vD);
            }
        }
    }

    // ---- epilogue: horizontal add, normalize, stage, residual write ----
    __syncthreads();                 // everyone done reading Ps; reuse as Os[64][132]
    float* Os = Ps;
    #pragma unroll
    for (int r = 0; r < 16; r++) {
        float rl = 1.0f / l[r];
        float a0, a1, b0, b1;
        up2(O2[r][0], a0, a1);
        up2(O2[r][1], b0, b1);
        Os[lane*132      + i0 + r] = (a0 + a1) * rl;
        Os[(lane+32)*132 + i0 + r] = (b0 + b1) * rl;
    }
    __syncthreads();

    const float g = gamma[0];
    const float* xb = x   + (size_t)b*CC*NN + ibase;
    float*       ob = out + (size_t)b*CC*NN + ibase;
    for (int idx4 = t; idx4 < 2048; idx4 += 256) {
        int c = idx4 >> 5, i4 = (idx4 & 31) << 2;
        float4 o4 = *(float4*)&Os[c*132 + i4];
        float4 x4 = *(const float4*)&xb[(size_t)c*NN + i4];
        o4.x = g*o4.x + x4.x;
        o4.y = g*o4.y + x4.y;
        o4.z = g*o4.z + x4.z;
        o4.w = g*o4.w + x4.w;
        *(float4*)&ob[(size_t)c*NN + i4] = o4;
    }
}

// ---------------------------------------------------------------------------
extern "C" void kernel_launch(void* const* d_in, const int* in_sizes, int n_in,
                              void* d_out, int out_size)
{
    const float* x     = (const float*)d_in[0];
    const float* Wq    = (const float*)d_in[1];
    const float* bq    = (const float*)d_in[2];
    const float* Wk    = (const float*)d_in[3];
    const float* bk    = (const float*)d_in[4];
    const float* Wv    = (const float*)d_in[5];
    const float* bv    = (const float*)d_in[6];
    const float* gamma = (const float*)d_in[7];
    float* out = (float*)d_out;

    const int smem1 = (64*128 + 3*64*68) * sizeof(float);   // 84,992 B
    const int smem2 = 40960 * sizeof(float);                // 163,840 B

    cudaFuncSetAttribute(qkv_kernel,  cudaFuncAttributeMaxDynamicSharedMemorySize, smem1);
    cudaFuncSetAttribute(attn_kernel, cudaFuncAttributeMaxDynamicSharedMemorySize, smem2);

    qkv_kernel<<<dim3(32, 4), 256, smem1>>>(x, Wq, bq, Wk, bk, Wv, bv);
    attn_kernel<<<dim3(32, 4), 256, smem2>>>(x, gamma, out);
}